// round 5
// baseline (speedup 1.0000x reference)
#include <cuda_runtime.h>
#include <cstdint>

#define BB 8
#define NN 8192
#define MM 2048
#define NUM_ITER 4
#define BASE_ALPHA 0.1f

// Scratch: nearest point (xyz) + min_dist per (b,n); per-iter per-batch max bits.
__device__ float4 g_near[BB * NN];
__device__ int    g_maxbits[NUM_ITER * BB];

// ---------------------------------------------------------------------------
// f32x2 packed helpers (Blackwell FFMA2 path, PTX fma.rn.f32x2)
// ---------------------------------------------------------------------------
__device__ __forceinline__ uint64_t pack2(float lo, float hi) {
    uint64_t r;
    asm("mov.b64 %0, {%1, %2};" : "=l"(r) : "f"(lo), "f"(hi));
    return r;
}
__device__ __forceinline__ uint64_t ffma2(uint64_t a, uint64_t b, uint64_t c) {
    uint64_t d;
    asm("fma.rn.f32x2 %0, %1, %2, %3;" : "=l"(d) : "l"(a), "l"(b), "l"(c));
    return d;
}
__device__ __forceinline__ void unpack2(uint64_t v, float& lo, float& hi) {
    asm("mov.b64 {%0, %1}, %2;" : "=f"(lo), "=f"(hi) : "l"(v));
}

// ---------------------------------------------------------------------------
// Init: copy pred -> out, zero max slots.
// ---------------------------------------------------------------------------
__global__ void ipgr_init_kernel(const float4* __restrict__ pred,
                                 float4* __restrict__ out) {
    int i = blockIdx.x * blockDim.x + threadIdx.x;
    if (i < NUM_ITER * BB) g_maxbits[i] = 0;
    const int total4 = BB * NN * 3 / 4;  // 49152 float4
    for (; i < total4; i += gridDim.x * blockDim.x) out[i] = pred[i];
}

// ---------------------------------------------------------------------------
// NN search with fused application of previous iteration's blend (iter>=1).
// block = 128 threads (4 warps), grid = (NN/128, BB) = (64, 8) = 512 blocks.
// Lane layout: q = lane>>3 (M-quarter), sub = lane&7; 4 points per thread.
// Argmin: 2 slots per point; each slot covers one POSITION PAIR {2j, 2j+1}
// inside the 4-m quad. Inner update per slot: FMNMX tournament of the pair,
// then one strict-< compare against the running best (keeps earliest k).
// The position within the winning pair is recovered after the loop by
// bit-exact recomputation of t at (k*, pos 2j): identical fma order/rounding
// makes the equality test exact; equality -> lower position, preserving the
// reference's first-index tie rule at every level.
// Comparison key: t = |y|^2/2 - x.y (argmin-equivalent; |x|^2 const/point).
// ---------------------------------------------------------------------------
__global__ void __launch_bounds__(128)
ipgr_nn_kernel(float* __restrict__ refined,
               const float* __restrict__ partial,
               int iter) {
    // SoA tile of partial: yx | yy | yz | yh(=0.5*|y|^2), each MM floats.
    __shared__ __align__(16) float sm[4 * MM];
    __shared__ float smax[4];

    const int b = blockIdx.y;
    const float* p = partial + (size_t)b * MM * 3;

    for (int m = threadIdx.x; m < MM; m += 128) {
        float yx = p[m * 3 + 0];
        float yy = p[m * 3 + 1];
        float yz = p[m * 3 + 2];
        sm[m]          = yx;
        sm[MM + m]     = yy;
        sm[2 * MM + m] = yz;
        sm[3 * MM + m] = 0.5f * fmaf(yz, yz, fmaf(yy, yy, yx * yx));
    }
    __syncthreads();

    const int lane = threadIdx.x & 31;
    const int warp = threadIdx.x >> 5;
    const int q    = lane >> 3;
    const int sub  = lane & 7;
    const int n0   = blockIdx.x * 128 + warp * 32 + sub * 4;  // 4 points/thread

    // Prologue: load 4 pred points; iter>0 applies previous blend inline
    // (per-batch max complete at kernel boundary). All q-lanes compute the
    // identical update; q==0 stores back (warp-exclusive point ownership).
    uint64_t xp0[4], xp1[4], xp2[4];  // packed (-x, -x)
    float xs[4];
    {
        float* rp = refined + ((size_t)b * NN + n0) * 3;
        float mxp = 1.0f;
        if (iter > 0)
            mxp = __int_as_float(g_maxbits[(iter - 1) * BB + b]) + 1e-6f;
#pragma unroll
        for (int i = 0; i < 4; i++) {
            float x0 = rp[i * 3 + 0];
            float x1 = rp[i * 3 + 1];
            float x2 = rp[i * 3 + 2];
            if (iter > 0) {
                float4 nd = g_near[b * NN + n0 + i];
                float alpha = BASE_ALPHA * (2.0f - nd.w / mxp);
                x0 = fmaf(alpha, nd.x - x0, x0);
                x1 = fmaf(alpha, nd.y - x1, x1);
                x2 = fmaf(alpha, nd.z - x2, x2);
                if (q == 0) {
                    rp[i * 3 + 0] = x0;
                    rp[i * 3 + 1] = x1;
                    rp[i * 3 + 2] = x2;
                }
            }
            xp0[i] = pack2(-x0, -x0);
            xp1[i] = pack2(-x1, -x1);
            xp2[i] = pack2(-x2, -x2);
            xs[i]  = fmaf(x2, x2, fmaf(x1, x1, x0 * x0));
        }
    }

    // 2 slots per point: slot j covers positions {2j, 2j+1} of each quad.
    float best[4][2];
    int   bkk[4][2];
#pragma unroll
    for (int i = 0; i < 4; i++) {
        best[i][0] = 3.4e38f; best[i][1] = 3.4e38f;
        bkk[i][0] = 0;        bkk[i][1] = 0;
    }

    const ulonglong2* pyx = reinterpret_cast<const ulonglong2*>(sm)          + q * 128;
    const ulonglong2* pyy = reinterpret_cast<const ulonglong2*>(sm + MM)     + q * 128;
    const ulonglong2* pyz = reinterpret_cast<const ulonglong2*>(sm + 2 * MM) + q * 128;
    const ulonglong2* pyh = reinterpret_cast<const ulonglong2*>(sm + 3 * MM) + q * 128;
    const int mbase = q * 512;

#pragma unroll 2
    for (int k = 0; k < 128; k++) {
        ulonglong2 vx = pyx[k];
        ulonglong2 vy = pyy[k];
        ulonglong2 vz = pyz[k];
        ulonglong2 vh = pyh[k];
#pragma unroll
        for (int i = 0; i < 4; i++) {
            uint64_t t01 = ffma2(xp0[i], vx.x, vh.x);
            t01 = ffma2(xp1[i], vy.x, t01);
            t01 = ffma2(xp2[i], vz.x, t01);
            uint64_t t23 = ffma2(xp0[i], vx.y, vh.y);
            t23 = ffma2(xp1[i], vy.y, t23);
            t23 = ffma2(xp2[i], vz.y, t23);
            float t0, t1, t2, t3;
            unpack2(t01, t0, t1);
            unpack2(t23, t2, t3);
            float m01 = fminf(t0, t1);             // FMNMX
            float m23 = fminf(t2, t3);
            bool c0 = m01 < best[i][0];            // strict: earliest k kept
            best[i][0] = c0 ? m01 : best[i][0];
            bkk[i][0]  = c0 ? k   : bkk[i][0];
            bool c1 = m23 < best[i][1];
            best[i][1] = c1 ? m23 : best[i][1];
            bkk[i][1]  = c1 ? k   : bkk[i][1];
        }
    }

    // Resolve per-point winner: recover position within the winning pair by
    // bit-exact recomputation, then merge slots (value, then smaller m).
    float bv[4];
    int   bm[4];
#pragma unroll
    for (int i = 0; i < 4; i++) {
        float nx0, nx1, nx2, dumm;
        unpack2(xp0[i], nx0, dumm);
        unpack2(xp1[i], nx1, dumm);
        unpack2(xp2[i], nx2, dumm);
        float v[2];
        int   mm[2];
#pragma unroll
        for (int j = 0; j < 2; j++) {
            int mA = mbase + bkk[i][j] * 4 + 2 * j;
            // exact same op order/rounding as the loop's ffma2 lanes
            float tA = fmaf(nx2, sm[2 * MM + mA],
                       fmaf(nx1, sm[MM + mA],
                       fmaf(nx0, sm[mA], sm[3 * MM + mA])));
            v[j]  = best[i][j];
            mm[j] = (tA == best[i][j]) ? mA : (mA + 1);
        }
        bv[i] = v[0];
        bm[i] = mm[0];
        if (v[1] < bv[i] || (v[1] == bv[i] && mm[1] < bm[i])) {
            bv[i] = v[1];
            bm[i] = mm[1];
        }
    }

    // Merge the 4 M-quarters across lanes (bits 3,4). Tie -> smaller m.
#pragma unroll
    for (int r = 8; r <= 16; r <<= 1) {
#pragma unroll
        for (int i = 0; i < 4; i++) {
            float ob = __shfl_xor_sync(0xffffffffu, bv[i], r);
            int   oi = __shfl_xor_sync(0xffffffffu, bm[i], r);
            if (ob < bv[i] || (ob == bv[i] && oi < bm[i])) { bv[i] = ob; bm[i] = oi; }
        }
    }

    // Lanes with q==0 hold final results; write nearest + min_dist.
    float mloc = 0.0f;
    if (q == 0) {
#pragma unroll
        for (int i = 0; i < 4; i++) {
            int mi = bm[i];
            float d2 = fmaf(2.0f, bv[i], xs[i]);
            float md = sqrtf(fmaxf(d2, 0.0f));
            g_near[b * NN + n0 + i] =
                make_float4(sm[mi], sm[MM + mi], sm[2 * MM + mi], md);
            mloc = fmaxf(mloc, md);
        }
    }

    // Warp max, then block max via smem, one atomic per block.
#pragma unroll
    for (int o = 16; o > 0; o >>= 1)
        mloc = fmaxf(mloc, __shfl_xor_sync(0xffffffffu, mloc, o));
    if (lane == 0) smax[warp] = mloc;
    __syncthreads();
    if (threadIdx.x == 0) {
        float m01 = fmaxf(smax[0], smax[1]);
        float m23 = fmaxf(smax[2], smax[3]);
        atomicMax(&g_maxbits[iter * BB + b],
                  __float_as_int(fmaxf(m01, m23)));
    }
}

// ---------------------------------------------------------------------------
// Final blend (applies the last iteration's update).
// ---------------------------------------------------------------------------
__global__ void ipgr_update_kernel(float* __restrict__ refined, int iter) {
    const int gi = blockIdx.x * blockDim.x + threadIdx.x;  // b*NN + n
    const int b  = gi >> 13;  // NN = 8192

    float4 nd = g_near[gi];
    float  mx = __int_as_float(g_maxbits[iter * BB + b]);
    float  alpha = BASE_ALPHA * (2.0f - nd.w / (mx + 1e-6f));

    float r0 = refined[gi * 3 + 0];
    float r1 = refined[gi * 3 + 1];
    float r2 = refined[gi * 3 + 2];
    refined[gi * 3 + 0] = fmaf(alpha, nd.x - r0, r0);
    refined[gi * 3 + 1] = fmaf(alpha, nd.y - r1, r1);
    refined[gi * 3 + 2] = fmaf(alpha, nd.z - r2, r2);
}

// ---------------------------------------------------------------------------
extern "C" void kernel_launch(void* const* d_in, const int* in_sizes, int n_in,
                              void* d_out, int out_size) {
    const float* pred    = (const float*)d_in[0];  // [8, 8192, 3] f32
    const float* partial = (const float*)d_in[1];  // [8, 2048, 3] f32
    float* out = (float*)d_out;                     // [8, 8192, 3] f32

    (void)in_sizes; (void)n_in; (void)out_size;

    ipgr_init_kernel<<<192, 256>>>((const float4*)pred, (float4*)out);

    dim3 gridA(NN / 128, BB);  // (64, 8) = 512 blocks
    for (int it = 0; it < NUM_ITER; it++)
        ipgr_nn_kernel<<<gridA, 128>>>(out, partial, it);

    ipgr_update_kernel<<<(BB * NN) / 256, 256>>>(out, NUM_ITER - 1);
}

// round 6
// speedup vs baseline: 1.3215x; 1.3215x over previous
#include <cuda_runtime.h>
#include <cstdint>

#define BB 8
#define NN 8192
#define MM 2048
#define NUM_ITER 4
#define BASE_ALPHA 0.1f

// Scratch: nearest point (xyz) + min_dist per (b,n); per-iter per-batch max bits.
__device__ float4 g_near[BB * NN];
__device__ int    g_maxbits[NUM_ITER * BB];

// ---------------------------------------------------------------------------
// Init: copy pred -> out, zero max slots.
// ---------------------------------------------------------------------------
__global__ void ipgr_init_kernel(const float4* __restrict__ pred,
                                 float4* __restrict__ out) {
    int i = blockIdx.x * blockDim.x + threadIdx.x;
    if (i < NUM_ITER * BB) g_maxbits[i] = 0;
    const int total4 = BB * NN * 3 / 4;  // 49152 float4
    for (; i < total4; i += gridDim.x * blockDim.x) out[i] = pred[i];
}

// ---------------------------------------------------------------------------
// NN search with fused application of previous iteration's blend (iter>=1).
// block = 128 threads (4 warps), grid = (NN/128, BB) = (64, 8) = 512 blocks.
// Lane layout: q = lane>>3 (M-quarter), sub = lane&7; 4 points per thread.
// ALL-SCALAR FFMA inner loop (no f32x2): R1 evidence shows scalar FFMA
// sustains ~75% issue where FFMA2 variants cap at ~50% (64-bit operand
// register-bank pressure).
// Argmin: per point, 2 slots (position pairs {0,1} and {2,3} of each 4-m
// quad); within a slot compares are sequential with strict < , so the
// first (smallest m) among equals wins at every level — exact reference
// tie-break. Cross-slot and cross-lane merges compare (value, then m).
// Comparison key: t = |y|^2/2 - x.y (argmin-equivalent; |x|^2 const/point).
// ---------------------------------------------------------------------------
__global__ void __launch_bounds__(128)
ipgr_nn_kernel(float* __restrict__ refined,
               const float* __restrict__ partial,
               int iter) {
    // SoA tile of partial: yx | yy | yz | yh(=0.5*|y|^2), each MM floats.
    __shared__ __align__(16) float sx[MM];
    __shared__ __align__(16) float sy_[MM];
    __shared__ __align__(16) float sz[MM];
    __shared__ __align__(16) float sh[MM];
    __shared__ float smax[4];

    const int b = blockIdx.y;
    const float* p = partial + (size_t)b * MM * 3;

    for (int m = threadIdx.x; m < MM; m += 128) {
        float yx = p[m * 3 + 0];
        float yy = p[m * 3 + 1];
        float yz = p[m * 3 + 2];
        sx[m]  = yx;
        sy_[m] = yy;
        sz[m]  = yz;
        sh[m]  = 0.5f * fmaf(yz, yz, fmaf(yy, yy, yx * yx));
    }
    __syncthreads();

    const int lane = threadIdx.x & 31;
    const int warp = threadIdx.x >> 5;
    const int q    = lane >> 3;
    const int sub  = lane & 7;
    const int n0   = blockIdx.x * 128 + warp * 32 + sub * 4;  // 4 points/thread

    // Prologue: load 4 pred points; iter>0 applies previous blend inline
    // (per-batch max complete at kernel boundary). All q-lanes compute the
    // identical update; q==0 stores back (warp-exclusive point ownership).
    float nx0[4], nx1[4], nx2[4];  // negated coords: t = yh + (-x).y
    float xs[4];
    {
        float* rp = refined + ((size_t)b * NN + n0) * 3;
        float mxp = 1.0f;
        if (iter > 0)
            mxp = __int_as_float(g_maxbits[(iter - 1) * BB + b]) + 1e-6f;
#pragma unroll
        for (int i = 0; i < 4; i++) {
            float x0 = rp[i * 3 + 0];
            float x1 = rp[i * 3 + 1];
            float x2 = rp[i * 3 + 2];
            if (iter > 0) {
                float4 nd = g_near[b * NN + n0 + i];
                float alpha = BASE_ALPHA * (2.0f - nd.w / mxp);
                x0 = fmaf(alpha, nd.x - x0, x0);
                x1 = fmaf(alpha, nd.y - x1, x1);
                x2 = fmaf(alpha, nd.z - x2, x2);
                if (q == 0) {
                    rp[i * 3 + 0] = x0;
                    rp[i * 3 + 1] = x1;
                    rp[i * 3 + 2] = x2;
                }
            }
            nx0[i] = -x0;
            nx1[i] = -x1;
            nx2[i] = -x2;
            xs[i]  = fmaf(x2, x2, fmaf(x1, x1, x0 * x0));
        }
    }

    // 2 slots per point: slot 0 covers positions {0,1}, slot 1 covers {2,3}.
    float best[4][2];
    int   bm4[4][2];  // stores full m index
#pragma unroll
    for (int i = 0; i < 4; i++) {
        best[i][0] = 3.4e38f; best[i][1] = 3.4e38f;
        bm4[i][0] = 0;        bm4[i][1] = 0;
    }

    const float4* pyx = reinterpret_cast<const float4*>(sx)  + q * 128;
    const float4* pyy = reinterpret_cast<const float4*>(sy_) + q * 128;
    const float4* pyz = reinterpret_cast<const float4*>(sz)  + q * 128;
    const float4* pyh = reinterpret_cast<const float4*>(sh)  + q * 128;
    const int mbase = q * 512;

#pragma unroll 2
    for (int k = 0; k < 128; k++) {
        float4 vx = pyx[k];
        float4 vy = pyy[k];
        float4 vz = pyz[k];
        float4 vh = pyh[k];
        const int m0 = mbase + k * 4;
#pragma unroll
        for (int i = 0; i < 4; i++) {
            float t0 = fmaf(nx2[i], vz.x, fmaf(nx1[i], vy.x, fmaf(nx0[i], vx.x, vh.x)));
            float t1 = fmaf(nx2[i], vz.y, fmaf(nx1[i], vy.y, fmaf(nx0[i], vx.y, vh.y)));
            float t2 = fmaf(nx2[i], vz.z, fmaf(nx1[i], vy.z, fmaf(nx0[i], vx.z, vh.z)));
            float t3 = fmaf(nx2[i], vz.w, fmaf(nx1[i], vy.w, fmaf(nx0[i], vx.w, vh.w)));
            // slot 0: positions 0 then 1 (strict < keeps first/smallest m)
            bool c0 = t0 < best[i][0];
            best[i][0] = c0 ? t0 : best[i][0];
            bm4[i][0]  = c0 ? m0 : bm4[i][0];
            bool c1 = t1 < best[i][0];
            best[i][0] = c1 ? t1 : best[i][0];
            bm4[i][0]  = c1 ? (m0 + 1) : bm4[i][0];
            // slot 1: positions 2 then 3
            bool c2 = t2 < best[i][1];
            best[i][1] = c2 ? t2 : best[i][1];
            bm4[i][1]  = c2 ? (m0 + 2) : bm4[i][1];
            bool c3 = t3 < best[i][1];
            best[i][1] = c3 ? t3 : best[i][1];
            bm4[i][1]  = c3 ? (m0 + 3) : bm4[i][1];
        }
    }

    // Merge the 2 slots per point (value, then smaller m).
    float bv[4];
    int   bm[4];
#pragma unroll
    for (int i = 0; i < 4; i++) {
        bv[i] = best[i][0];
        bm[i] = bm4[i][0];
        float v1 = best[i][1];
        int   m1 = bm4[i][1];
        if (v1 < bv[i] || (v1 == bv[i] && m1 < bm[i])) { bv[i] = v1; bm[i] = m1; }
    }

    // Merge the 4 M-quarters across lanes (bits 3,4). Tie -> smaller m.
#pragma unroll
    for (int r = 8; r <= 16; r <<= 1) {
#pragma unroll
        for (int i = 0; i < 4; i++) {
            float ob = __shfl_xor_sync(0xffffffffu, bv[i], r);
            int   oi = __shfl_xor_sync(0xffffffffu, bm[i], r);
            if (ob < bv[i] || (ob == bv[i] && oi < bm[i])) { bv[i] = ob; bm[i] = oi; }
        }
    }

    // Lanes with q==0 hold final results; write nearest + min_dist.
    float mloc = 0.0f;
    if (q == 0) {
#pragma unroll
        for (int i = 0; i < 4; i++) {
            int mi = bm[i];
            float d2 = fmaf(2.0f, bv[i], xs[i]);
            float md = sqrtf(fmaxf(d2, 0.0f));
            g_near[b * NN + n0 + i] = make_float4(sx[mi], sy_[mi], sz[mi], md);
            mloc = fmaxf(mloc, md);
        }
    }

    // Warp max, then block max via smem, one atomic per block.
#pragma unroll
    for (int o = 16; o > 0; o >>= 1)
        mloc = fmaxf(mloc, __shfl_xor_sync(0xffffffffu, mloc, o));
    if (lane == 0) smax[warp] = mloc;
    __syncthreads();
    if (threadIdx.x == 0) {
        float m01 = fmaxf(smax[0], smax[1]);
        float m23 = fmaxf(smax[2], smax[3]);
        atomicMax(&g_maxbits[iter * BB + b],
                  __float_as_int(fmaxf(m01, m23)));
    }
}

// ---------------------------------------------------------------------------
// Final blend (applies the last iteration's update).
// ---------------------------------------------------------------------------
__global__ void ipgr_update_kernel(float* __restrict__ refined, int iter) {
    const int gi = blockIdx.x * blockDim.x + threadIdx.x;  // b*NN + n
    const int b  = gi >> 13;  // NN = 8192

    float4 nd = g_near[gi];
    float  mx = __int_as_float(g_maxbits[iter * BB + b]);
    float  alpha = BASE_ALPHA * (2.0f - nd.w / (mx + 1e-6f));

    float r0 = refined[gi * 3 + 0];
    float r1 = refined[gi * 3 + 1];
    float r2 = refined[gi * 3 + 2];
    refined[gi * 3 + 0] = fmaf(alpha, nd.x - r0, r0);
    refined[gi * 3 + 1] = fmaf(alpha, nd.y - r1, r1);
    refined[gi * 3 + 2] = fmaf(alpha, nd.z - r2, r2);
}

// ---------------------------------------------------------------------------
extern "C" void kernel_launch(void* const* d_in, const int* in_sizes, int n_in,
                              void* d_out, int out_size) {
    const float* pred    = (const float*)d_in[0];  // [8, 8192, 3] f32
    const float* partial = (const float*)d_in[1];  // [8, 2048, 3] f32
    float* out = (float*)d_out;                     // [8, 8192, 3] f32

    (void)in_sizes; (void)n_in; (void)out_size;

    ipgr_init_kernel<<<192, 256>>>((const float4*)pred, (float4*)out);

    dim3 gridA(NN / 128, BB);  // (64, 8) = 512 blocks
    for (int it = 0; it < NUM_ITER; it++)
        ipgr_nn_kernel<<<gridA, 128>>>(out, partial, it);

    ipgr_update_kernel<<<(BB * NN) / 256, 256>>>(out, NUM_ITER - 1);
}

// round 7
// speedup vs baseline: 1.8490x; 1.3992x over previous
#include <cuda_runtime.h>
#include <cstdint>

#define BB 8
#define NN 8192
#define MM 2048
#define NUM_ITER 4
#define BASE_ALPHA 0.1f

// Scratch: nearest point (xyz) + min_dist per (b,n); per-iter per-batch max bits.
__device__ float4 g_near[BB * NN];
__device__ int    g_maxbits[NUM_ITER * BB];

// ---------------------------------------------------------------------------
// f32x2 packed helpers (Blackwell FFMA2 path, PTX fma.rn.f32x2)
// ---------------------------------------------------------------------------
__device__ __forceinline__ uint64_t pack2(float lo, float hi) {
    uint64_t r;
    asm("mov.b64 %0, {%1, %2};" : "=l"(r) : "f"(lo), "f"(hi));
    return r;
}
__device__ __forceinline__ uint64_t ffma2(uint64_t a, uint64_t b, uint64_t c) {
    uint64_t d;
    asm("fma.rn.f32x2 %0, %1, %2, %3;" : "=l"(d) : "l"(a), "l"(b), "l"(c));
    return d;
}
__device__ __forceinline__ void unpack2(uint64_t v, float& lo, float& hi) {
    asm("mov.b64 {%0, %1}, %2;" : "=f"(lo), "=f"(hi) : "l"(v));
}

// ---------------------------------------------------------------------------
// Init: copy pred -> out, zero max slots.
// ---------------------------------------------------------------------------
__global__ void ipgr_init_kernel(const float4* __restrict__ pred,
                                 float4* __restrict__ out) {
    int i = blockIdx.x * blockDim.x + threadIdx.x;
    if (i < NUM_ITER * BB) g_maxbits[i] = 0;
    const int total4 = BB * NN * 3 / 4;  // 49152 float4
    for (; i < total4; i += gridDim.x * blockDim.x) out[i] = pred[i];
}

// ---------------------------------------------------------------------------
// NN search with fused application of previous iteration's blend (iter>=1).
// block = 128 threads (4 warps), grid = (NN/128, BB) = (64, 8) = 512 blocks.
// Lane layout: q = lane>>3 (M-quarter), sub = lane&7; 4 points per thread.
// Math: FFMA2 (R2's best-measured config). Argmin: VALUE-ONLY quad
// tournament (3 FMNMX per quad) tracking only the quad index k; position
// within the winning quad recovered after the loop by bit-exact scalar
// recomputation (scalar fma.rn == each f32x2 lane), scanning positions
// 3..0 so the smallest matching position wins -> exact first-index
// tie-break. Strict < across k keeps the earliest quad.
// Comparison key: t = |y|^2/2 - x.y (argmin-equivalent; |x|^2 const/point).
// ---------------------------------------------------------------------------
__global__ void __launch_bounds__(128)
ipgr_nn_kernel(float* __restrict__ refined,
               const float* __restrict__ partial,
               int iter) {
    // SoA tile of partial: yx | yy | yz | yh(=0.5*|y|^2), each MM floats.
    __shared__ __align__(16) float sm[4 * MM];
    __shared__ float smax[4];

    const int b = blockIdx.y;
    const float* p = partial + (size_t)b * MM * 3;

    for (int m = threadIdx.x; m < MM; m += 128) {
        float yx = p[m * 3 + 0];
        float yy = p[m * 3 + 1];
        float yz = p[m * 3 + 2];
        sm[m]          = yx;
        sm[MM + m]     = yy;
        sm[2 * MM + m] = yz;
        sm[3 * MM + m] = 0.5f * fmaf(yz, yz, fmaf(yy, yy, yx * yx));
    }
    __syncthreads();

    const int lane = threadIdx.x & 31;
    const int warp = threadIdx.x >> 5;
    const int q    = lane >> 3;
    const int sub  = lane & 7;
    const int n0   = blockIdx.x * 128 + warp * 32 + sub * 4;  // 4 points/thread

    // Prologue: load 4 pred points; iter>0 applies previous blend inline
    // (per-batch max complete at kernel boundary). All q-lanes compute the
    // identical update; q==0 stores back (warp-exclusive point ownership).
    uint64_t xp0[4], xp1[4], xp2[4];  // packed (-x, -x)
    float xs[4];
    {
        float* rp = refined + ((size_t)b * NN + n0) * 3;
        float mxp = 1.0f;
        if (iter > 0)
            mxp = __int_as_float(g_maxbits[(iter - 1) * BB + b]) + 1e-6f;
#pragma unroll
        for (int i = 0; i < 4; i++) {
            float x0 = rp[i * 3 + 0];
            float x1 = rp[i * 3 + 1];
            float x2 = rp[i * 3 + 2];
            if (iter > 0) {
                float4 nd = g_near[b * NN + n0 + i];
                float alpha = BASE_ALPHA * (2.0f - nd.w / mxp);
                x0 = fmaf(alpha, nd.x - x0, x0);
                x1 = fmaf(alpha, nd.y - x1, x1);
                x2 = fmaf(alpha, nd.z - x2, x2);
                if (q == 0) {
                    rp[i * 3 + 0] = x0;
                    rp[i * 3 + 1] = x1;
                    rp[i * 3 + 2] = x2;
                }
            }
            xp0[i] = pack2(-x0, -x0);
            xp1[i] = pack2(-x1, -x1);
            xp2[i] = pack2(-x2, -x2);
            xs[i]  = fmaf(x2, x2, fmaf(x1, x1, x0 * x0));
        }
    }

    // One accumulator per point: best quad-min value + its quad index k.
    float best[4] = {3.4e38f, 3.4e38f, 3.4e38f, 3.4e38f};
    int   bk[4]   = {0, 0, 0, 0};

    const ulonglong2* pyx = reinterpret_cast<const ulonglong2*>(sm)          + q * 128;
    const ulonglong2* pyy = reinterpret_cast<const ulonglong2*>(sm + MM)     + q * 128;
    const ulonglong2* pyz = reinterpret_cast<const ulonglong2*>(sm + 2 * MM) + q * 128;
    const ulonglong2* pyh = reinterpret_cast<const ulonglong2*>(sm + 3 * MM) + q * 128;
    const int mbase = q * 512;

#pragma unroll 2
    for (int k = 0; k < 128; k++) {
        ulonglong2 vx = pyx[k];
        ulonglong2 vy = pyy[k];
        ulonglong2 vz = pyz[k];
        ulonglong2 vh = pyh[k];
#pragma unroll
        for (int i = 0; i < 4; i++) {
            uint64_t t01 = ffma2(xp0[i], vx.x, vh.x);
            t01 = ffma2(xp1[i], vy.x, t01);
            t01 = ffma2(xp2[i], vz.x, t01);
            uint64_t t23 = ffma2(xp0[i], vx.y, vh.y);
            t23 = ffma2(xp1[i], vy.y, t23);
            t23 = ffma2(xp2[i], vz.y, t23);
            float t0, t1, t2, t3;
            unpack2(t01, t0, t1);
            unpack2(t23, t2, t3);
            float qmin = fminf(fminf(t0, t1), fminf(t2, t3));  // 3 FMNMX
            bool c = qmin < best[i];   // strict: earliest quad kept
            best[i] = c ? qmin : best[i];
            bk[i]   = c ? k    : bk[i];
        }
    }

    // Recover the position within each point's winning quad by bit-exact
    // scalar recomputation (same fma order/rounding as the f32x2 lanes).
    // Scan 3..0 so the smallest matching position survives.
    float bv[4];
    int   bm[4];
#pragma unroll
    for (int i = 0; i < 4; i++) {
        float nx0, nx1, nx2, du;
        unpack2(xp0[i], nx0, du);
        unpack2(xp1[i], nx1, du);
        unpack2(xp2[i], nx2, du);
        const int m0 = mbase + bk[i] * 4;
        int pos = 3;
#pragma unroll
        for (int j = 2; j >= 0; j--) {
            int mj = m0 + j;
            float tj = fmaf(nx2, sm[2 * MM + mj],
                       fmaf(nx1, sm[MM + mj],
                       fmaf(nx0, sm[mj], sm[3 * MM + mj])));
            if (tj == best[i]) pos = j;
        }
        bv[i] = best[i];
        bm[i] = m0 + pos;
    }

    // Merge the 4 M-quarters across lanes (bits 3,4). Tie -> smaller m.
#pragma unroll
    for (int r = 8; r <= 16; r <<= 1) {
#pragma unroll
        for (int i = 0; i < 4; i++) {
            float ob = __shfl_xor_sync(0xffffffffu, bv[i], r);
            int   oi = __shfl_xor_sync(0xffffffffu, bm[i], r);
            if (ob < bv[i] || (ob == bv[i] && oi < bm[i])) { bv[i] = ob; bm[i] = oi; }
        }
    }

    // Lanes with q==0 hold final results; write nearest + min_dist.
    float mloc = 0.0f;
    if (q == 0) {
#pragma unroll
        for (int i = 0; i < 4; i++) {
            int mi = bm[i];
            float d2 = fmaf(2.0f, bv[i], xs[i]);
            float md = sqrtf(fmaxf(d2, 0.0f));
            g_near[b * NN + n0 + i] =
                make_float4(sm[mi], sm[MM + mi], sm[2 * MM + mi], md);
            mloc = fmaxf(mloc, md);
        }
    }

    // Warp max, then block max via smem, one atomic per block.
#pragma unroll
    for (int o = 16; o > 0; o >>= 1)
        mloc = fmaxf(mloc, __shfl_xor_sync(0xffffffffu, mloc, o));
    if (lane == 0) smax[warp] = mloc;
    __syncthreads();
    if (threadIdx.x == 0) {
        float m01 = fmaxf(smax[0], smax[1]);
        float m23 = fmaxf(smax[2], smax[3]);
        atomicMax(&g_maxbits[iter * BB + b],
                  __float_as_int(fmaxf(m01, m23)));
    }
}

// ---------------------------------------------------------------------------
// Final blend (applies the last iteration's update).
// ---------------------------------------------------------------------------
__global__ void ipgr_update_kernel(float* __restrict__ refined, int iter) {
    const int gi = blockIdx.x * blockDim.x + threadIdx.x;  // b*NN + n
    const int b  = gi >> 13;  // NN = 8192

    float4 nd = g_near[gi];
    float  mx = __int_as_float(g_maxbits[iter * BB + b]);
    float  alpha = BASE_ALPHA * (2.0f - nd.w / (mx + 1e-6f));

    float r0 = refined[gi * 3 + 0];
    float r1 = refined[gi * 3 + 1];
    float r2 = refined[gi * 3 + 2];
    refined[gi * 3 + 0] = fmaf(alpha, nd.x - r0, r0);
    refined[gi * 3 + 1] = fmaf(alpha, nd.y - r1, r1);
    refined[gi * 3 + 2] = fmaf(alpha, nd.z - r2, r2);
}

// ---------------------------------------------------------------------------
extern "C" void kernel_launch(void* const* d_in, const int* in_sizes, int n_in,
                              void* d_out, int out_size) {
    const float* pred    = (const float*)d_in[0];  // [8, 8192, 3] f32
    const float* partial = (const float*)d_in[1];  // [8, 2048, 3] f32
    float* out = (float*)d_out;                     // [8, 8192, 3] f32

    (void)in_sizes; (void)n_in; (void)out_size;

    ipgr_init_kernel<<<192, 256>>>((const float4*)pred, (float4*)out);

    dim3 gridA(NN / 128, BB);  // (64, 8) = 512 blocks
    for (int it = 0; it < NUM_ITER; it++)
        ipgr_nn_kernel<<<gridA, 128>>>(out, partial, it);

    ipgr_update_kernel<<<(BB * NN) / 256, 256>>>(out, NUM_ITER - 1);
}